// round 2
// baseline (speedup 1.0000x reference)
#include <cuda_runtime.h>
#include <math.h>

#define Bb 8
#define Hh 128
#define Ww 128
#define Cc 768
#define NB 8
#define BS 96
#define WF 65
#define LAMBDA 0.01f
#define SQRT_INV 0.088388347648318447f  /* 1/sqrt(128) */

#define SA 132   /* row stride (floats) of A tile in k_mid */
#define SO 200   /* row stride (floats) of O1 tile in k_mid */
#define SMEM_MID ((192*SA + 128*SO + 16*192 + 192 + 192 + 128) * 4)

/* scratch spectrum buffer: (B, Wf, H, C) complex, reused in place by K2 */
__device__ float2 g_Xw[(size_t)Bb * WF * Hh * Cc];

__device__ __forceinline__ int brev7(int x) { return (int)(__brev((unsigned)x) >> 25); }

/* ================= K1: rfft along W =================
   x (B,H,W,C) -> g_Xw (B,Wf,H,C), ortho scale 1/sqrt(128).
   Packs channel pairs (2f, 2f+1) into one complex FFT.
   Load with bit-reversed placement, in-place DIT -> natural-order spectrum. */
__global__ __launch_bounds__(256) void k_rfft_w(const float* __restrict__ x) {
    __shared__ float2 tw[64];
    __shared__ float Z[16 * 258];  /* 16 FFTs x 129 complex (padded), as floats */
    int tid = threadIdx.x;
    if (tid < 64) {
        float sn, cs;
        sincosf(-6.283185307179586f * (float)tid / 128.0f, &sn, &cs);
        tw[tid] = make_float2(cs, sn);
    }
    int cg = blockIdx.x, h = blockIdx.y, b = blockIdx.z;
    int c0 = cg * 32;
    const float* xp = x + ((size_t)(b * Hh + h)) * Ww * Cc + c0;

    for (int idx = tid; idx < 128 * 32; idx += 256) {
        int w = idx >> 5, c = idx & 31;
        float v = xp[(size_t)w * Cc + c];
        int f = c >> 1;
        Z[f * 258 + brev7(w) * 2 + (c & 1)] = v;
    }
    __syncthreads();

    /* forward DIT (bitrev in -> natural out) */
    for (int s = 0; s < 7; s++) {
        int half = 1 << s;
        for (int t = tid; t < 1024; t += 256) {
            int f = t >> 6, q = t & 63;
            int g = q >> s, j = q & (half - 1);
            int i0 = (g << (s + 1)) + j, i1 = i0 + half;
            float2 w = tw[j << (6 - s)];
            float* base = Z + f * 258;
            float ar = base[2 * i0], ai = base[2 * i0 + 1];
            float br = base[2 * i1], bi = base[2 * i1 + 1];
            float tr = br * w.x - bi * w.y;
            float ti = br * w.y + bi * w.x;
            base[2 * i0] = ar + tr; base[2 * i0 + 1] = ai + ti;
            base[2 * i1] = ar - tr; base[2 * i1 + 1] = ai - ti;
        }
        __syncthreads();
    }

    /* unpack two real spectra from each packed FFT, store */
    for (int idx = tid; idx < 65 * 32; idx += 256) {
        int k = idx >> 5, c = idx & 31;
        int f = c >> 1, m = (128 - k) & 127;
        float* base = Z + f * 258;
        float zkr = base[2 * k], zki = base[2 * k + 1];
        float zmr = base[2 * m], zmi = base[2 * m + 1];
        float2 v;
        if ((c & 1) == 0) v = make_float2(0.5f * (zkr + zmr), 0.5f * (zki - zmi));
        else              v = make_float2(0.5f * (zki + zmi), -0.5f * (zkr - zmr));
        v.x *= SQRT_INV; v.y *= SQRT_INV;
        g_Xw[(((size_t)b * WF + k) * Hh + h) * Cc + c0 + c] = v;
    }
}

/* ================= K2: fused FFT-H + block MLP + iFFT-H (in place) =================
   One block per (n, wf, b). Tile = 128 h x 96 channels complex.
   A smem tile layout: rows 0..95 = real(channel c) over h, rows 96..191 = imag.
   Forward DIF (natural->bitrev), per-position MLP (order agnostic), inverse DIT
   with conjugate twiddles (bitrev->natural). No bit reversal needed anywhere. */
__global__ __launch_bounds__(256) void k_mid(const float* __restrict__ w1g,
                                             const float* __restrict__ b1g,
                                             const float* __restrict__ w2g,
                                             const float* __restrict__ b2g) {
    extern __shared__ float sm[];
    float* A   = sm;                       /* 192 x SA */
    float* O1  = A + 192 * SA;             /* 128 x SO */
    float* Wst = O1 + 128 * SO;            /* 16 x 192 */
    float* b1c = Wst + 16 * 192;           /* 192 */
    float* b2c = b1c + 192;                /* 192 */
    float2* tw = (float2*)(b2c + 192);     /* 64 */

    int tid = threadIdx.x;
    int n = blockIdx.x, wf = blockIdx.y, b = blockIdx.z;

    if (tid < 64) {
        float sn, cs;
        sincosf(-6.283185307179586f * (float)tid / 128.0f, &sn, &cs);
        tw[tid] = make_float2(cs, sn);
    }
    if (tid >= 64 && tid < 256) {
        int o = tid - 64;
        if (o < 192) {
            b1c[o] = (o < 96) ? b1g[n * 96 + o] : b1g[NB * 96 + n * 96 + (o - 96)];
            b2c[o] = (o < 96) ? b2g[n * 96 + o] : b2g[NB * 96 + n * 96 + (o - 96)];
        }
    }

    /* load tile (natural h order) */
    for (int idx = tid; idx < 128 * 96; idx += 256) {
        int c = idx % 96, h = idx / 96;
        float2 v = g_Xw[(((size_t)b * WF + wf) * Hh + h) * Cc + n * BS + c];
        A[c * SA + h]        = v.x * SQRT_INV;
        A[(96 + c) * SA + h] = v.y * SQRT_INV;
    }
    __syncthreads();

    /* forward DIF over h for 96 complex channels (natural in -> bitrev out) */
    for (int s = 6; s >= 0; s--) {
        int half = 1 << s;
        for (int t = tid; t < 6144; t += 256) {
            int c = t >> 6, q = t & 63;
            int g = q >> s, j = q & (half - 1);
            int i0 = (g << (s + 1)) + j, i1 = i0 + half;
            float2 w = tw[j << (6 - s)];
            float* R = A + c * SA;
            float* I = A + (96 + c) * SA;
            float ar = R[i0], ai = I[i0], br = R[i1], bi = I[i1];
            float dr = ar - br, di = ai - bi;
            R[i0] = ar + br; I[i0] = ai + bi;
            R[i1] = dr * w.x - di * w.y;
            I[i1] = dr * w.y + di * w.x;
        }
        __syncthreads();
    }

    /* ---- MLP layer 1: o1[h][o] = relu( sum_i A[i][h] * W1c[i][o] + b1c[o] ) ---- */
    int og = tid & 15, hg = tid >> 4;
    int o0 = og * 12, h0 = hg * 8;
    float acc[96];
#pragma unroll
    for (int q = 0; q < 96; q++) acc[q] = 0.f;

    const float* w1n0 = w1g + (size_t)n * BS * BS;                        /* w1[0][n] */
    const float* w1n1 = w1g + (size_t)NB * BS * BS + (size_t)n * BS * BS; /* w1[1][n] */

    for (int ch = 0; ch < 12; ch++) {
        for (int widx = tid; widx < 16 * 192; widx += 256) {
            int o = widx % 192, ii = widx / 192;
            int i = ch * 16 + ii;
            float v;
            if (i < 96) v = (o < 96) ? w1n0[i * 96 + o] : w1n1[i * 96 + (o - 96)];
            else { int i2 = i - 96; v = (o < 96) ? -w1n1[i2 * 96 + o] : w1n0[i2 * 96 + (o - 96)]; }
            Wst[ii * 192 + o] = v;
        }
        __syncthreads();
#pragma unroll
        for (int ii = 0; ii < 16; ii++) {
            int i = ch * 16 + ii;
            const float* Ar = A + i * SA + h0;
            float4 a0 = *(const float4*)(Ar);
            float4 a1 = *(const float4*)(Ar + 4);
            float av[8] = {a0.x, a0.y, a0.z, a0.w, a1.x, a1.y, a1.z, a1.w};
            const float* Wr = Wst + ii * 192 + o0;
            float wv[12];
#pragma unroll
            for (int u = 0; u < 12; u += 4) {
                float4 wq = *(const float4*)(Wr + u);
                wv[u] = wq.x; wv[u + 1] = wq.y; wv[u + 2] = wq.z; wv[u + 3] = wq.w;
            }
#pragma unroll
            for (int r = 0; r < 8; r++)
#pragma unroll
                for (int u = 0; u < 12; u++)
                    acc[r * 12 + u] = fmaf(av[r], wv[u], acc[r * 12 + u]);
        }
        __syncthreads();
    }
#pragma unroll
    for (int r = 0; r < 8; r++)
#pragma unroll
        for (int u = 0; u < 12; u++) {
            float v = acc[r * 12 + u] + b1c[o0 + u];
            O1[(h0 + r) * SO + o0 + u] = fmaxf(v, 0.f);
        }
    __syncthreads();

    /* ---- MLP layer 2: o2[h][i] = softshrink( sum_o O1[h][o] * W2c[o][i] + b2c[i] ) ---- */
#pragma unroll
    for (int q = 0; q < 96; q++) acc[q] = 0.f;
    const float* w2n0 = w2g + (size_t)n * BS * BS;
    const float* w2n1 = w2g + (size_t)NB * BS * BS + (size_t)n * BS * BS;

    for (int ch = 0; ch < 12; ch++) {
        for (int widx = tid; widx < 16 * 192; widx += 256) {
            int o = widx % 192, ii = widx / 192;
            int i = ch * 16 + ii; /* contraction index (o1 feature) */
            float v;
            if (i < 96) v = (o < 96) ? w2n0[i * 96 + o] : w2n1[i * 96 + (o - 96)];
            else { int i2 = i - 96; v = (o < 96) ? -w2n1[i2 * 96 + o] : w2n0[i2 * 96 + (o - 96)]; }
            Wst[ii * 192 + o] = v;
        }
        __syncthreads();
#pragma unroll
        for (int ii = 0; ii < 16; ii++) {
            int i = ch * 16 + ii;
            float av[8];
#pragma unroll
            for (int r = 0; r < 8; r++) av[r] = O1[(h0 + r) * SO + i];
            const float* Wr = Wst + ii * 192 + o0;
            float wv[12];
#pragma unroll
            for (int u = 0; u < 12; u += 4) {
                float4 wq = *(const float4*)(Wr + u);
                wv[u] = wq.x; wv[u + 1] = wq.y; wv[u + 2] = wq.z; wv[u + 3] = wq.w;
            }
#pragma unroll
            for (int r = 0; r < 8; r++)
#pragma unroll
                for (int u = 0; u < 12; u++)
                    acc[r * 12 + u] = fmaf(av[r], wv[u], acc[r * 12 + u]);
        }
        __syncthreads();
    }
    /* bias + softshrink + transpose back into A ([feature][h]) */
#pragma unroll
    for (int u = 0; u < 12; u++) {
        int i = o0 + u;
        float bb = b2c[i];
        float vv[8];
#pragma unroll
        for (int r = 0; r < 8; r++) {
            float v = acc[r * 12 + u] + bb;
            vv[r] = (v > LAMBDA) ? (v - LAMBDA) : ((v < -LAMBDA) ? (v + LAMBDA) : 0.f);
        }
        float* Ar = A + i * SA + h0;
        *(float4*)(Ar)     = make_float4(vv[0], vv[1], vv[2], vv[3]);
        *(float4*)(Ar + 4) = make_float4(vv[4], vv[5], vv[6], vv[7]);
    }
    __syncthreads();

    /* inverse DIT with conjugate twiddles (bitrev in -> natural out) */
    for (int s = 0; s < 7; s++) {
        int half = 1 << s;
        for (int t = tid; t < 6144; t += 256) {
            int c = t >> 6, q = t & 63;
            int g = q >> s, j = q & (half - 1);
            int i0 = (g << (s + 1)) + j, i1 = i0 + half;
            float2 w = tw[j << (6 - s)];
            float* R = A + c * SA;
            float* I = A + (96 + c) * SA;
            float br = R[i1], bi = I[i1];
            float tr = br * w.x + bi * w.y;   /* b * conj(w) */
            float ti = bi * w.x - br * w.y;
            float ar = R[i0], ai = I[i0];
            R[i0] = ar + tr; I[i0] = ai + ti;
            R[i1] = ar - tr; I[i1] = ai - ti;
        }
        __syncthreads();
    }

    /* store back in place (natural h), ortho scale */
    for (int idx = tid; idx < 128 * 96; idx += 256) {
        int c = idx % 96, h = idx / 96;
        float2 v = make_float2(A[c * SA + h] * SQRT_INV, A[(96 + c) * SA + h] * SQRT_INV);
        g_Xw[(((size_t)b * WF + wf) * Hh + h) * Cc + n * BS + c] = v;
    }
}

/* ================= K3: irfft along W + residual =================
   g_Xw (B,Wf,H,C) -> y (B,H,W,C); y = irfft + x.
   Hermitian-extends and packs channel pairs into one complex iFFT.
   NOTE: like pocketfft/cuFFT C2R, the imaginary parts of bins k=0 and k=64
   must be IGNORED (halfcomplex format has no storage for them). */
__global__ __launch_bounds__(256) void k_irfft_w(const float* __restrict__ x,
                                                 float* __restrict__ y) {
    __shared__ float2 tw[64];
    __shared__ float Z[16 * 258];
    __shared__ float4 S[16 * 65];  /* raw (a, b) half-spectra per packed FFT */
    int tid = threadIdx.x;
    if (tid < 64) {
        float sn, cs;
        sincosf(-6.283185307179586f * (float)tid / 128.0f, &sn, &cs);
        tw[tid] = make_float2(cs, sn);
    }
    int cg = blockIdx.x, h = blockIdx.y, b = blockIdx.z;
    int c0 = cg * 32;

    /* load half-spectra of channel pair (c0+2f, c0+2f+1) as one float4 */
    for (int idx = tid; idx < 16 * 65; idx += 256) {
        int f = idx & 15, k = idx >> 4;
        S[f * 65 + k] = *(const float4*)&g_Xw[(((size_t)b * WF + k) * Hh + h) * Cc + c0 + 2 * f];
    }
    __syncthreads();

    /* build packed full spectrum Z[k] = A_k + i*B_k with Hermitian extension.
       At k=0 and k=64 drop imag(A), imag(B) (C2R semantics). */
    for (int idx = tid; idx < 16 * 128; idx += 256) {
        int f = idx >> 7, k = idx & 127;
        float zr, zi;
        if (k <= 64) {
            float4 s = S[f * 65 + k];
            if (k == 0 || k == 64) { zr = s.x; zi = s.z; }
            else                   { zr = s.x - s.w; zi = s.y + s.z; }
        } else {
            float4 s = S[f * 65 + (128 - k)];
            zr = s.x + s.w; zi = s.z - s.y;
        }
        Z[f * 258 + 2 * k] = zr;
        Z[f * 258 + 2 * k + 1] = zi;
    }
    __syncthreads();

    /* inverse DIF, conj twiddles (natural in -> bitrev out) */
    for (int s = 6; s >= 0; s--) {
        int half = 1 << s;
        for (int t = tid; t < 1024; t += 256) {
            int f = t >> 6, q = t & 63;
            int g = q >> s, j = q & (half - 1);
            int i0 = (g << (s + 1)) + j, i1 = i0 + half;
            float2 w = tw[j << (6 - s)];
            float* base = Z + f * 258;
            float ar = base[2 * i0], ai = base[2 * i0 + 1];
            float br = base[2 * i1], bi = base[2 * i1 + 1];
            float dr = ar - br, di = ai - bi;
            base[2 * i0] = ar + br; base[2 * i0 + 1] = ai + bi;
            base[2 * i1] = dr * w.x + di * w.y;   /* (a-b)*conj(w) */
            base[2 * i1 + 1] = di * w.x - dr * w.y;
        }
        __syncthreads();
    }

    /* store: real part -> even channel, imag part -> odd channel; add residual */
    const float* xp = x + ((size_t)(b * Hh + h)) * Ww * Cc + c0;
    float* yp = y + ((size_t)(b * Hh + h)) * Ww * Cc + c0;
    for (int idx = tid; idx < 128 * 32; idx += 256) {
        int p = idx >> 5, c = idx & 31;
        int w = brev7(p);
        int f = c >> 1;
        float v = Z[f * 258 + 2 * p + (c & 1)];
        yp[(size_t)w * Cc + c] = v * SQRT_INV + xp[(size_t)w * Cc + c];
    }
}

extern "C" void kernel_launch(void* const* d_in, const int* in_sizes, int n_in,
                              void* d_out, int out_size) {
    (void)in_sizes; (void)n_in; (void)out_size;
    const float* x  = (const float*)d_in[0];
    const float* w1 = (const float*)d_in[1];
    const float* b1 = (const float*)d_in[2];
    const float* w2 = (const float*)d_in[3];
    const float* b2 = (const float*)d_in[4];
    float* y = (float*)d_out;

    cudaFuncSetAttribute(k_mid, cudaFuncAttributeMaxDynamicSharedMemorySize, SMEM_MID);

    k_rfft_w<<<dim3(24, Hh, Bb), 256>>>(x);
    k_mid<<<dim3(NB, WF, Bb), 256, SMEM_MID>>>(w1, b1, w2, b2);
    k_irfft_w<<<dim3(24, Hh, Bb), 256>>>(x, y);
}

// round 3
// speedup vs baseline: 1.8999x; 1.8999x over previous
#include <cuda_runtime.h>
#include <cuda_bf16.h>
#include <math.h>
#include <stdint.h>

#define Bb 8
#define Hh 128
#define Ww 128
#define Cc 768
#define NB 8
#define BS 96
#define WF 65
#define LAMBDA 0.01f
#define SQRT_INV 0.088388347648318447f  /* 1/sqrt(128) */

#define SA 134   /* fp32 row stride of A tile in k_mid */
#define XS 200   /* bf16 row stride for Xb / O1b / Wt */

#define NFLOATS_A (192 * SA)            /* 25728 floats = 102912 B  */
#define WT_OFF    NFLOATS_A             /* Wt: 192*XS bf16 = 76800 B */
#define WT_FLOATS (192 * XS / 2)        /* 19200 */
#define B1_OFF    (WT_OFF + WT_FLOATS)
#define B2_OFF    (B1_OFF + 192)
#define TW_OFF    (B2_OFF + 192)
#define SMEM_MID  ((TW_OFF + 128) * 4)  /* 181760 B */

/* scratch spectrum buffer: (B, Wf, H, C) complex */
__device__ float2 g_Xw[(size_t)Bb * WF * Hh * Cc];

__device__ __forceinline__ int brev7(int x) { return (int)(__brev((unsigned)x) >> 25); }

__device__ __forceinline__ uint32_t pack_bf16(float a, float b) {
    __nv_bfloat162 t = __floats2bfloat162_rn(a, b);
    return *(uint32_t*)&t;
}

__device__ __forceinline__ void mma_bf16(float* d,
    uint32_t a0, uint32_t a1, uint32_t a2, uint32_t a3, uint32_t b0, uint32_t b1)
{
    asm volatile(
        "mma.sync.aligned.m16n8k16.row.col.f32.bf16.bf16.f32 "
        "{%0,%1,%2,%3}, {%4,%5,%6,%7}, {%8,%9}, {%0,%1,%2,%3};\n"
        : "+f"(d[0]), "+f"(d[1]), "+f"(d[2]), "+f"(d[3])
        : "r"(a0), "r"(a1), "r"(a2), "r"(a3), "r"(b0), "r"(b1));
}

/* GEMM: [128h x 192k] (bf16, Am row-major stride XS) @ W^T (Bt[n][k] bf16 stride XS)
   Each warp: 16 h rows (m0), one n-half (96 cols = 12 n-tiles), full k (12 k-tiles). */
__device__ __forceinline__ void gemm_192(const __nv_bfloat16* __restrict__ Am,
                                         const __nv_bfloat16* __restrict__ Bt,
                                         float acc[12][4], int m0, int nh, int g, int tg)
{
#pragma unroll
    for (int kt = 0; kt < 12; kt++) {
        const __nv_bfloat16* ap = Am + (m0 + g) * XS + kt * 16 + tg * 2;
        uint32_t a0 = *(const uint32_t*)(ap);
        uint32_t a1 = *(const uint32_t*)(ap + 8 * XS);
        uint32_t a2 = *(const uint32_t*)(ap + 8);
        uint32_t a3 = *(const uint32_t*)(ap + 8 * XS + 8);
#pragma unroll
        for (int nt = 0; nt < 12; nt++) {
            const __nv_bfloat16* bp = Bt + (nh * 96 + nt * 8 + g) * XS + kt * 16 + tg * 2;
            uint32_t b0 = *(const uint32_t*)(bp);
            uint32_t b1 = *(const uint32_t*)(bp + 8);
            mma_bf16(acc[nt], a0, a1, a2, a3, b0, b1);
        }
    }
}

/* ================= K1: rfft along W ================= */
__global__ __launch_bounds__(256) void k_rfft_w(const float* __restrict__ x) {
    __shared__ float2 tw[64];
    __shared__ float2 z[16 * 129];
    int tid = threadIdx.x;
    if (tid < 64) {
        float sn, cs;
        sincosf(-6.283185307179586f * (float)tid / 128.0f, &sn, &cs);
        tw[tid] = make_float2(cs, sn);
    }
    int cg = blockIdx.x, h = blockIdx.y, b = blockIdx.z;
    int c0 = cg * 32;
    const float* xp = x + ((size_t)(b * Hh + h)) * Ww * Cc + c0;

    for (int idx = tid; idx < 128 * 32; idx += 256) {
        int w = idx >> 5, c = idx & 31;
        float v = xp[(size_t)w * Cc + c];
        int f = c >> 1;
        ((float*)&z[f * 129 + brev7(w)])[c & 1] = v;
    }
    __syncthreads();

    for (int s = 0; s < 7; s++) {
        int half = 1 << s;
        for (int t = tid; t < 1024; t += 256) {
            int f = t & 15, q = t >> 4;
            int gq = q >> s, j = q & (half - 1);
            int i0 = (gq << (s + 1)) + j, i1 = i0 + half;
            float2 w = tw[j << (6 - s)];
            float2* zz = z + f * 129;
            float2 a = zz[i0], bv = zz[i1];
            float tr = bv.x * w.x - bv.y * w.y;
            float ti = bv.x * w.y + bv.y * w.x;
            zz[i0] = make_float2(a.x + tr, a.y + ti);
            zz[i1] = make_float2(a.x - tr, a.y - ti);
        }
        __syncthreads();
    }

    for (int idx = tid; idx < 65 * 32; idx += 256) {
        int k = idx >> 5, c = idx & 31;
        int f = c >> 1, m = (128 - k) & 127;
        float2 zk = z[f * 129 + k], zm = z[f * 129 + m];
        float2 v;
        if ((c & 1) == 0) v = make_float2(0.5f * (zk.x + zm.x), 0.5f * (zk.y - zm.y));
        else              v = make_float2(0.5f * (zk.y + zm.y), -0.5f * (zk.x - zm.x));
        v.x *= SQRT_INV; v.y *= SQRT_INV;
        g_Xw[(((size_t)b * WF + k) * Hh + h) * Cc + c0 + c] = v;
    }
}

/* ================= K2: fused FFT-H + bf16 tensor-core MLP + iFFT-H ================= */
__global__ __launch_bounds__(512) void k_mid(const float* __restrict__ w1g,
                                             const float* __restrict__ b1g,
                                             const float* __restrict__ w2g,
                                             const float* __restrict__ b2g) {
    extern __shared__ float sm[];
    float* A = sm;                                        /* 192 x SA fp32 */
    __nv_bfloat16* Xb  = (__nv_bfloat16*)sm;              /* overlay: 128 x XS */
    __nv_bfloat16* O1b = (__nv_bfloat16*)sm + 128 * XS;   /* overlay: 128 x XS */
    __nv_bfloat16* Wt  = (__nv_bfloat16*)(sm + WT_OFF);   /* 192 x XS */
    float* b1c = sm + B1_OFF;
    float* b2c = sm + B2_OFF;
    float2* tw = (float2*)(sm + TW_OFF);

    int tid = threadIdx.x;
    int n = blockIdx.x, wf = blockIdx.y, b = blockIdx.z;
    int warp = tid >> 5, lane = tid & 31;
    int g = lane >> 2, tg = lane & 3;
    int m0 = (warp >> 1) * 16, nh = warp & 1;

    if (tid < 64) {
        float sn, cs;
        sincosf(-6.283185307179586f * (float)tid / 128.0f, &sn, &cs);
        tw[tid] = make_float2(cs, sn);
    }
    if (tid >= 64 && tid < 256) {
        int o = tid - 64;
        if (o < 192) b1c[o] = (o < 96) ? b1g[n * 96 + o] : b1g[NB * 96 + n * 96 + (o - 96)];
    }
    if (tid >= 256 && tid < 448) {
        int o = tid - 256;
        b2c[o] = (o < 96) ? b2g[n * 96 + o] : b2g[NB * 96 + n * 96 + (o - 96)];
    }

    /* ---- load tile (fp32, [feature][h]) ---- */
    size_t base = (((size_t)b * WF + wf) * Hh) * Cc + n * BS;
    for (int idx = tid; idx < 128 * 96; idx += 512) {
        int c = idx % 96, h = idx / 96;
        float2 v = g_Xw[base + (size_t)h * Cc + c];
        A[c * SA + h]        = v.x;
        A[(96 + c) * SA + h] = v.y;
    }
    __syncthreads();

    /* ---- forward DIF over h (natural in -> bitrev out) ---- */
    for (int s = 6; s >= 0; s--) {
        int half = 1 << s;
        for (int t = tid; t < 6144; t += 512) {
            int c = t >> 6, q = t & 63;
            int gq = q >> s, j = q & (half - 1);
            int i0 = (gq << (s + 1)) + j, i1 = i0 + half;
            float2 w = tw[j << (6 - s)];
            float* R = A + c * SA;
            float* I = A + (96 + c) * SA;
            float ar = R[i0], ai = I[i0], br = R[i1], bi = I[i1];
            float dr = ar - br, di = ai - bi;
            R[i0] = ar + br; I[i0] = ai + bi;
            R[i1] = dr * w.x - di * w.y;
            I[i1] = dr * w.y + di * w.x;
        }
        __syncthreads();
    }

    /* ---- convert A (fp32 [i][h]) -> Xb (bf16 [h][i]) with ortho scale.
           Xb overlays A, so stage through registers with a sync between. ---- */
    {
        float tmpv[48];
#pragma unroll
        for (int k = 0; k < 48; k++) {
            int idx = tid + k * 512;
            int h = idx & 127, i = idx >> 7;
            tmpv[k] = A[i * SA + h] * SQRT_INV;
        }
        __syncthreads();
#pragma unroll
        for (int k = 0; k < 48; k++) {
            int idx = tid + k * 512;
            int h = idx & 127, i = idx >> 7;
            Xb[h * XS + i] = __float2bfloat16(tmpv[k]);
        }
    }
    /* stage W1^T: Wt[o][i] = W1c[i][o] */
    {
        const float* w1n0 = w1g + (size_t)n * BS * BS;
        const float* w1n1 = w1g + (size_t)NB * BS * BS + (size_t)n * BS * BS;
        for (int widx = tid; widx < 192 * 192; widx += 512) {
            int o = widx % 192, i = widx / 192;
            float v;
            if (i < 96) v = (o < 96) ? w1n0[i * 96 + o] : w1n1[i * 96 + (o - 96)];
            else { int i2 = i - 96; v = (o < 96) ? -w1n1[i2 * 96 + o] : w1n0[i2 * 96 + (o - 96)]; }
            Wt[o * XS + i] = __float2bfloat16(v);
        }
    }
    __syncthreads();

    /* ---- GEMM1: O1 = relu(Xb @ W1c + b1) ---- */
    {
        float acc[12][4];
#pragma unroll
        for (int i = 0; i < 12; i++)
#pragma unroll
            for (int j2 = 0; j2 < 4; j2++) acc[i][j2] = 0.f;

        gemm_192(Xb, Wt, acc, m0, nh, g, tg);

#pragma unroll
        for (int nt = 0; nt < 12; nt++) {
            int o = nh * 96 + nt * 8 + tg * 2;
            float v0 = fmaxf(acc[nt][0] + b1c[o], 0.f);
            float v1 = fmaxf(acc[nt][1] + b1c[o + 1], 0.f);
            float v2 = fmaxf(acc[nt][2] + b1c[o], 0.f);
            float v3 = fmaxf(acc[nt][3] + b1c[o + 1], 0.f);
            *(uint32_t*)&O1b[(m0 + g) * XS + o]     = pack_bf16(v0, v1);
            *(uint32_t*)&O1b[(m0 + g + 8) * XS + o] = pack_bf16(v2, v3);
        }
    }
    __syncthreads();

    /* stage W2^T: Wt[j][o] = W2c[o][j] (overwrites W1t) */
    {
        const float* w2n0 = w2g + (size_t)n * BS * BS;
        const float* w2n1 = w2g + (size_t)NB * BS * BS + (size_t)n * BS * BS;
        for (int widx = tid; widx < 192 * 192; widx += 512) {
            int o = widx % 192, i = widx / 192;
            float v;
            if (i < 96) v = (o < 96) ? w2n0[i * 96 + o] : w2n1[i * 96 + (o - 96)];
            else { int i2 = i - 96; v = (o < 96) ? -w2n1[i2 * 96 + o] : w2n0[i2 * 96 + (o - 96)]; }
            Wt[o * XS + i] = __float2bfloat16(v);
        }
    }
    __syncthreads();

    /* ---- GEMM2: o2 = softshrink(O1 @ W2c + b2) * SQRT_INV, write fp32 into A ---- */
    {
        float acc[12][4];
#pragma unroll
        for (int i = 0; i < 12; i++)
#pragma unroll
            for (int j2 = 0; j2 < 4; j2++) acc[i][j2] = 0.f;

        gemm_192(O1b, Wt, acc, m0, nh, g, tg);

        __syncthreads();   /* all warps done reading O1b/Xb before A is overwritten */

#pragma unroll
        for (int nt = 0; nt < 12; nt++) {
            int j = nh * 96 + nt * 8 + tg * 2;
            float v0 = acc[nt][0] + b2c[j];
            float v1 = acc[nt][1] + b2c[j + 1];
            float v2 = acc[nt][2] + b2c[j];
            float v3 = acc[nt][3] + b2c[j + 1];
            v0 = ((v0 > LAMBDA) ? v0 - LAMBDA : ((v0 < -LAMBDA) ? v0 + LAMBDA : 0.f)) * SQRT_INV;
            v1 = ((v1 > LAMBDA) ? v1 - LAMBDA : ((v1 < -LAMBDA) ? v1 + LAMBDA : 0.f)) * SQRT_INV;
            v2 = ((v2 > LAMBDA) ? v2 - LAMBDA : ((v2 < -LAMBDA) ? v2 + LAMBDA : 0.f)) * SQRT_INV;
            v3 = ((v3 > LAMBDA) ? v3 - LAMBDA : ((v3 < -LAMBDA) ? v3 + LAMBDA : 0.f)) * SQRT_INV;
            A[j * SA + m0 + g]           = v0;
            A[(j + 1) * SA + m0 + g]     = v1;
            A[j * SA + m0 + g + 8]       = v2;
            A[(j + 1) * SA + m0 + g + 8] = v3;
        }
    }
    __syncthreads();

    /* ---- inverse DIT, conj twiddles (bitrev in -> natural out) ---- */
    for (int s = 0; s < 7; s++) {
        int half = 1 << s;
        for (int t = tid; t < 6144; t += 512) {
            int c = t >> 6, q = t & 63;
            int gq = q >> s, j = q & (half - 1);
            int i0 = (gq << (s + 1)) + j, i1 = i0 + half;
            float2 w = tw[j << (6 - s)];
            float* R = A + c * SA;
            float* I = A + (96 + c) * SA;
            float br = R[i1], bi = I[i1];
            float tr = br * w.x + bi * w.y;
            float ti = bi * w.x - br * w.y;
            float ar = R[i0], ai = I[i0];
            R[i0] = ar + tr; I[i0] = ai + ti;
            R[i1] = ar - tr; I[i1] = ai - ti;
        }
        __syncthreads();
    }

    /* ---- store back (scales already folded) ---- */
    for (int idx = tid; idx < 128 * 96; idx += 512) {
        int c = idx % 96, h = idx / 96;
        g_Xw[base + (size_t)h * Cc + c] = make_float2(A[c * SA + h], A[(96 + c) * SA + h]);
    }
}

/* ================= K3: irfft along W + residual ================= */
__global__ __launch_bounds__(256) void k_irfft_w(const float* __restrict__ x,
                                                 float* __restrict__ y) {
    __shared__ float2 tw[64];
    __shared__ float2 z[16 * 129];
    __shared__ float4 S[16 * 65];
    int tid = threadIdx.x;
    if (tid < 64) {
        float sn, cs;
        sincosf(-6.283185307179586f * (float)tid / 128.0f, &sn, &cs);
        tw[tid] = make_float2(cs, sn);
    }
    int cg = blockIdx.x, h = blockIdx.y, b = blockIdx.z;
    int c0 = cg * 32;

    for (int idx = tid; idx < 16 * 65; idx += 256) {
        int f = idx & 15, k = idx >> 4;
        S[f * 65 + k] = *(const float4*)&g_Xw[(((size_t)b * WF + k) * Hh + h) * Cc + c0 + 2 * f];
    }
    __syncthreads();

    /* packed full spectrum with Hermitian extension; C2R semantics at k=0,64 */
    for (int idx = tid; idx < 16 * 128; idx += 256) {
        int f = idx >> 7, k = idx & 127;
        float zr, zi;
        if (k <= 64) {
            float4 s = S[f * 65 + k];
            if (k == 0 || k == 64) { zr = s.x; zi = s.z; }
            else                   { zr = s.x - s.w; zi = s.y + s.z; }
        } else {
            float4 s = S[f * 65 + (128 - k)];
            zr = s.x + s.w; zi = s.z - s.y;
        }
        z[f * 129 + k] = make_float2(zr, zi);
    }
    __syncthreads();

    for (int s = 6; s >= 0; s--) {
        int half = 1 << s;
        for (int t = tid; t < 1024; t += 256) {
            int f = t & 15, q = t >> 4;
            int gq = q >> s, j = q & (half - 1);
            int i0 = (gq << (s + 1)) + j, i1 = i0 + half;
            float2 w = tw[j << (6 - s)];
            float2* zz = z + f * 129;
            float2 a = zz[i0], bv = zz[i1];
            float dr = a.x - bv.x, di = a.y - bv.y;
            zz[i0] = make_float2(a.x + bv.x, a.y + bv.y);
            zz[i1] = make_float2(dr * w.x + di * w.y, di * w.x - dr * w.y);
        }
        __syncthreads();
    }

    const float* xp = x + ((size_t)(b * Hh + h)) * Ww * Cc + c0;
    float* yp = y + ((size_t)(b * Hh + h)) * Ww * Cc + c0;
    for (int idx = tid; idx < 128 * 32; idx += 256) {
        int p = idx >> 5, c = idx & 31;
        int w = brev7(p);
        int f = c >> 1;
        float v = ((float*)&z[f * 129 + p])[c & 1];
        yp[(size_t)w * Cc + c] = v * SQRT_INV + xp[(size_t)w * Cc + c];
    }
}

extern "C" void kernel_launch(void* const* d_in, const int* in_sizes, int n_in,
                              void* d_out, int out_size) {
    (void)in_sizes; (void)n_in; (void)out_size;
    const float* x  = (const float*)d_in[0];
    const float* w1 = (const float*)d_in[1];
    const float* b1 = (const float*)d_in[2];
    const float* w2 = (const float*)d_in[3];
    const float* b2 = (const float*)d_in[4];
    float* y = (float*)d_out;

    cudaFuncSetAttribute(k_mid, cudaFuncAttributeMaxDynamicSharedMemorySize, SMEM_MID);

    k_rfft_w<<<dim3(24, Hh, Bb), 256>>>(x);
    k_mid<<<dim3(NB, WF, Bb), 512, SMEM_MID>>>(w1, b1, w2, b2);
    k_irfft_w<<<dim3(24, Hh, Bb), 256>>>(x, y);
}